// round 1
// baseline (speedup 1.0000x reference)
#include <cuda_runtime.h>
#include <cuda_bf16.h>
#include <math.h>

// Problem constants
#define BB   8
#define CC   256
#define HW   40000          // 200*200
#define HW4  10000          // HW / 4
#define KK   8000           // int(0.2 * HW)

// Scratch (allocation-free rule: __device__ globals)
__device__ unsigned g_score_u[BB * HW];   // float bits of sum(x^2) (nonneg -> uint order == float order)
__device__ float    g_sim[BB * HW];       // per-pixel cosine similarity
__device__ unsigned g_thresh[BB];         // k-th largest score (bit pattern)
__device__ int      g_needed[BB];         // how many ties at threshold to include
__device__ int      g_tie[BB];            // tie admission counters
__device__ double   g_sum;                // sum of selected sims

__global__ void k_init() {
    if (threadIdx.x < BB) g_tie[threadIdx.x] = 0;
    if (threadIdx.x == 0) g_sum = 0.0;
}

// ---------------------------------------------------------------------------
// Kernel 1: fused per-pixel channel statistics -> score + cosine sim.
// One thread per float4 of pixels (4 adjacent pixels), loops over C=256.
// Streaming, coalesced 128-bit loads; this is the HBM-bound kernel.
// ---------------------------------------------------------------------------
__global__ void __launch_bounds__(256) k_stats(const float* __restrict__ bev,
                                               const float* __restrict__ pri) {
    int idx = blockIdx.x * blockDim.x + threadIdx.x;
    if (idx >= BB * HW4) return;
    int b  = idx / HW4;
    int p4 = idx - b * HW4;

    const float4* pb = reinterpret_cast<const float4*>(bev + (size_t)b * CC * HW) + p4;
    const float4* pp = reinterpret_cast<const float4*>(pri + (size_t)b * CC * HW) + p4;

    float4 sb  = {0.f, 0.f, 0.f, 0.f};
    float4 sp  = {0.f, 0.f, 0.f, 0.f};
    float4 sbb = {0.f, 0.f, 0.f, 0.f};
    float4 spp = {0.f, 0.f, 0.f, 0.f};
    float4 sbp = {0.f, 0.f, 0.f, 0.f};

#pragma unroll 4
    for (int c = 0; c < CC; c++) {
        float4 x = __ldg(pb + c * HW4);
        float4 y = __ldg(pp + c * HW4);
#define ACC(f)                                \
        sb.f  += x.f;                         \
        sp.f  += y.f;                         \
        sbb.f  = fmaf(x.f, x.f, sbb.f);       \
        spp.f  = fmaf(y.f, y.f, spp.f);       \
        sbp.f  = fmaf(x.f, y.f, sbp.f);
        ACC(x) ACC(y) ACC(z) ACC(w)
#undef ACC
    }

    const float invC  = 1.0f / (float)CC;
    const float invC1 = 1.0f / (float)(CC - 1);
    int obase = b * HW + p4 * 4;

#define EMIT(f, j) {                                                        \
        float Sb = sb.f, Sp = sp.f, Sb2 = sbb.f, Sp2 = spp.f, Sxp = sbp.f;  \
        float SSb = fmaxf(Sb2 - Sb * Sb * invC, 0.0f);                      \
        float SSp = fmaxf(Sp2 - Sp * Sp * invC, 0.0f);                      \
        float Cov = Sxp - Sb * Sp * invC;                                   \
        float sgb = sqrtf(SSb * invC1) + 1e-6f;                             \
        float sgp = sqrtf(SSp * invC1) + 1e-6f;                             \
        float na  = sqrtf(SSb) / sgb;                                       \
        float nb  = sqrtf(SSp) / sgp;                                       \
        float sim = (Cov / (sgb * sgp)) /                                   \
                    (fmaxf(na, 1e-8f) * fmaxf(nb, 1e-8f));                  \
        g_score_u[obase + j] = __float_as_uint(Sb2);                        \
        g_sim[obase + j]     = sim;                                         \
    }
    EMIT(x, 0) EMIT(y, 1) EMIT(z, 2) EMIT(w, 3)
#undef EMIT
}

// ---------------------------------------------------------------------------
// Kernel 2: exact k-th largest per batch via 4-pass 8-bit radix select on the
// float bit patterns (scores are >= 0, so uint order == float order).
// One block per batch; score array (1.25 MB) sits in L2.
// ---------------------------------------------------------------------------
__global__ void __launch_bounds__(1024) k_select() {
    int b = blockIdx.x;
    const unsigned* s = g_score_u + b * HW;
    __shared__ unsigned hist[256];
    __shared__ unsigned sh_prefix;
    __shared__ int sh_k;
    if (threadIdx.x == 0) { sh_prefix = 0u; sh_k = KK; }
    __syncthreads();

    for (int pass = 0; pass < 4; pass++) {
        int shift = 24 - 8 * pass;
        unsigned mask = (pass == 0) ? 0u : (0xFFFFFFFFu << (shift + 8));
        for (int i = threadIdx.x; i < 256; i += blockDim.x) hist[i] = 0u;
        __syncthreads();
        unsigned prefix = sh_prefix;
        for (int i = threadIdx.x; i < HW; i += blockDim.x) {
            unsigned u = s[i];
            if ((u & mask) == prefix)
                atomicAdd(&hist[(u >> shift) & 255u], 1u);
        }
        __syncthreads();
        if (threadIdx.x == 0) {
            int kk = sh_k;
            int bin = 255;
            for (; bin > 0; bin--) {
                int c = (int)hist[bin];
                if (kk <= c) break;
                kk -= c;
            }
            sh_prefix = prefix | ((unsigned)bin << shift);
            sh_k = kk;
        }
        __syncthreads();
    }
    if (threadIdx.x == 0) { g_thresh[b] = sh_prefix; g_needed[b] = sh_k; }
}

// ---------------------------------------------------------------------------
// Kernel 3: sum sim over the top-k pixels (score > T always in; ties at T
// admitted up to 'needed' — with distinct scores this is exactly the tie set,
// so the result is deterministic).
// ---------------------------------------------------------------------------
__global__ void __launch_bounds__(256) k_topk_sum() {
    int b = blockIdx.x;
    unsigned T = g_thresh[b];
    int needed = g_needed[b];
    const unsigned* s   = g_score_u + b * HW;
    const float*    sim = g_sim     + b * HW;

    float local = 0.0f;
    int stride = blockDim.x * gridDim.y;
    for (int i = blockIdx.y * blockDim.x + threadIdx.x; i < HW; i += stride) {
        unsigned u = s[i];
        if (u > T) {
            local += sim[i];
        } else if (u == T) {
            int pos = atomicAdd(&g_tie[b], 1);
            if (pos < needed) local += sim[i];
        }
    }
    // block reduction
    __shared__ float red[256];
    red[threadIdx.x] = local;
    __syncthreads();
    for (int off = 128; off > 0; off >>= 1) {
        if (threadIdx.x < off) red[threadIdx.x] += red[threadIdx.x + off];
        __syncthreads();
    }
    if (threadIdx.x == 0) atomicAdd(&g_sum, (double)red[0]);
}

// ---------------------------------------------------------------------------
// Kernel 4: finalize -> scalar loss
// ---------------------------------------------------------------------------
__global__ void k_finalize(const float* __restrict__ dx,
                           const float* __restrict__ dy,
                           const float* __restrict__ dt,
                           float* __restrict__ out) {
    if (threadIdx.x == 0 && blockIdx.x == 0) {
        double mean_sim = g_sum / (double)(BB * KK);
        float align = (float)(1.0 - mean_sim);
        float r1 = 0.f, r2 = 0.f;
        for (int i = 0; i < BB; i++) {
            r1 += dx[i] * dx[i] + dy[i] * dy[i];
            r2 += dt[i] * dt[i];
        }
        float reg = r1 * (1.0f / BB) + r2 * (1.0f / BB);
        out[0] = align + 0.1f * reg;
    }
}

extern "C" void kernel_launch(void* const* d_in, const int* in_sizes, int n_in,
                              void* d_out, int out_size) {
    const float* bev = (const float*)d_in[0];
    const float* pri = (const float*)d_in[1];
    const float* dx  = (const float*)d_in[2];
    const float* dy  = (const float*)d_in[3];
    const float* dt  = (const float*)d_in[4];
    float* out = (float*)d_out;

    k_init<<<1, 32>>>();

    int total = BB * HW4;                 // 80000 threads
    int blocks = (total + 255) / 256;     // 313 blocks
    k_stats<<<blocks, 256>>>(bev, pri);

    k_select<<<BB, 1024>>>();

    dim3 g3(BB, 8, 1);
    k_topk_sum<<<g3, 256>>>();

    k_finalize<<<1, 32>>>(dx, dy, dt, out);
}

// round 2
// speedup vs baseline: 1.0541x; 1.0541x over previous
#include <cuda_runtime.h>
#include <cuda_bf16.h>
#include <math.h>

// Problem constants
#define BB   8
#define CC   256
#define HW   40000          // 200*200
#define HW4  10000          // HW / 4
#define KK   8000           // int(0.2 * HW)

// Scratch (allocation-free rule: __device__ globals)
__device__ unsigned g_score_u[BB * HW];   // float bits of sum(x^2) (nonneg -> uint order == float order)
__device__ float    g_sim[BB * HW];       // per-pixel cosine similarity
__device__ double   g_bsum[BB];           // per-batch sum of selected sims

// ---------------------------------------------------------------------------
// Kernel 1: fused per-pixel channel statistics -> score + cosine sim.
// One thread per float4 of pixels (4 adjacent pixels), loops over C=256.
// Streaming, coalesced 128-bit loads; this is the HBM-bound kernel.
// ---------------------------------------------------------------------------
__global__ void __launch_bounds__(256) k_stats(const float* __restrict__ bev,
                                               const float* __restrict__ pri) {
    int idx = blockIdx.x * blockDim.x + threadIdx.x;
    if (idx >= BB * HW4) return;
    int b  = idx / HW4;
    int p4 = idx - b * HW4;

    const float4* pb = reinterpret_cast<const float4*>(bev + (size_t)b * CC * HW) + p4;
    const float4* pp = reinterpret_cast<const float4*>(pri + (size_t)b * CC * HW) + p4;

    float4 sb  = {0.f, 0.f, 0.f, 0.f};
    float4 sp  = {0.f, 0.f, 0.f, 0.f};
    float4 sbb = {0.f, 0.f, 0.f, 0.f};
    float4 spp = {0.f, 0.f, 0.f, 0.f};
    float4 sbp = {0.f, 0.f, 0.f, 0.f};

#pragma unroll 4
    for (int c = 0; c < CC; c++) {
        float4 x = __ldg(pb + c * HW4);
        float4 y = __ldg(pp + c * HW4);
#define ACC(f)                                \
        sb.f  += x.f;                         \
        sp.f  += y.f;                         \
        sbb.f  = fmaf(x.f, x.f, sbb.f);       \
        spp.f  = fmaf(y.f, y.f, spp.f);       \
        sbp.f  = fmaf(x.f, y.f, sbp.f);
        ACC(x) ACC(y) ACC(z) ACC(w)
#undef ACC
    }

    const float invC  = 1.0f / (float)CC;
    const float invC1 = 1.0f / (float)(CC - 1);
    int obase = b * HW + p4 * 4;

#define EMIT(f, j) {                                                        \
        float Sb = sb.f, Sp = sp.f, Sb2 = sbb.f, Sp2 = spp.f, Sxp = sbp.f;  \
        float SSb = fmaxf(Sb2 - Sb * Sb * invC, 0.0f);                      \
        float SSp = fmaxf(Sp2 - Sp * Sp * invC, 0.0f);                      \
        float Cov = Sxp - Sb * Sp * invC;                                   \
        float sgb = sqrtf(SSb * invC1) + 1e-6f;                             \
        float sgp = sqrtf(SSp * invC1) + 1e-6f;                             \
        float na  = sqrtf(SSb) / sgb;                                       \
        float nb  = sqrtf(SSp) / sgp;                                       \
        float sim = (Cov / (sgb * sgp)) /                                   \
                    (fmaxf(na, 1e-8f) * fmaxf(nb, 1e-8f));                  \
        g_score_u[obase + j] = __float_as_uint(Sb2);                        \
        g_sim[obase + j]     = sim;                                         \
    }
    EMIT(x, 0) EMIT(y, 1) EMIT(z, 2) EMIT(w, 3)
#undef EMIT
}

// ---------------------------------------------------------------------------
// Kernel 2 (fused): exact k-th largest per batch via 4-pass 8-bit radix
// select on the float bit patterns (scores >= 0, uint order == float order),
// THEN sum sims over the top-k in the same block (data is L2-resident).
// One block per batch, 1024 threads. Writes per-batch sum race-free.
// ---------------------------------------------------------------------------
__global__ void __launch_bounds__(1024) k_select_sum() {
    int b = blockIdx.x;
    const unsigned* s   = g_score_u + b * HW;
    const float*    sim = g_sim     + b * HW;

    __shared__ unsigned hist[256];
    __shared__ unsigned sh_prefix;
    __shared__ int sh_k;
    __shared__ int sh_tie;
    __shared__ float red[32];

    if (threadIdx.x == 0) { sh_prefix = 0u; sh_k = KK; sh_tie = 0; }
    __syncthreads();

    // ---- radix select: find k-th largest score bit pattern ----
    for (int pass = 0; pass < 4; pass++) {
        int shift = 24 - 8 * pass;
        unsigned mask = (pass == 0) ? 0u : (0xFFFFFFFFu << (shift + 8));
        if (threadIdx.x < 256) hist[threadIdx.x] = 0u;
        __syncthreads();
        unsigned prefix = sh_prefix;
        for (int i = threadIdx.x; i < HW; i += 1024) {
            unsigned u = s[i];
            if ((u & mask) == prefix)
                atomicAdd(&hist[(u >> shift) & 255u], 1u);
        }
        __syncthreads();
        if (threadIdx.x == 0) {
            int kk = sh_k;
            int bin = 255;
            for (; bin > 0; bin--) {
                int c = (int)hist[bin];
                if (kk <= c) break;
                kk -= c;
            }
            sh_prefix = prefix | ((unsigned)bin << shift);
            sh_k = kk;
        }
        __syncthreads();
    }

    unsigned T = sh_prefix;
    int needed = sh_k;

    // ---- sum sims over top-k (score > T always; ties at T up to 'needed') ----
    float local = 0.0f;
    for (int i = threadIdx.x; i < HW; i += 1024) {
        unsigned u = s[i];
        if (u > T) {
            local += sim[i];
        } else if (u == T) {
            int pos = atomicAdd(&sh_tie, 1);
            if (pos < needed) local += sim[i];
        }
    }

    // block reduction: warp shuffle then cross-warp via shared
    for (int off = 16; off > 0; off >>= 1)
        local += __shfl_down_sync(0xFFFFFFFFu, local, off);
    int lane = threadIdx.x & 31;
    int wid  = threadIdx.x >> 5;
    if (lane == 0) red[wid] = local;
    __syncthreads();
    if (wid == 0) {
        float v = (lane < 32) ? red[lane] : 0.0f;
        for (int off = 16; off > 0; off >>= 1)
            v += __shfl_down_sync(0xFFFFFFFFu, v, off);
        if (lane == 0) g_bsum[b] = (double)v;
    }
}

// ---------------------------------------------------------------------------
// Kernel 3: finalize -> scalar loss
// ---------------------------------------------------------------------------
__global__ void k_finalize(const float* __restrict__ dx,
                           const float* __restrict__ dy,
                           const float* __restrict__ dt,
                           float* __restrict__ out) {
    if (threadIdx.x == 0 && blockIdx.x == 0) {
        double total = 0.0;
        for (int i = 0; i < BB; i++) total += g_bsum[i];
        double mean_sim = total / (double)(BB * KK);
        float align = (float)(1.0 - mean_sim);
        float r1 = 0.f, r2 = 0.f;
        for (int i = 0; i < BB; i++) {
            r1 += dx[i] * dx[i] + dy[i] * dy[i];
            r2 += dt[i] * dt[i];
        }
        float reg = r1 * (1.0f / BB) + r2 * (1.0f / BB);
        out[0] = align + 0.1f * reg;
    }
}

extern "C" void kernel_launch(void* const* d_in, const int* in_sizes, int n_in,
                              void* d_out, int out_size) {
    const float* bev = (const float*)d_in[0];
    const float* pri = (const float*)d_in[1];
    const float* dx  = (const float*)d_in[2];
    const float* dy  = (const float*)d_in[3];
    const float* dt  = (const float*)d_in[4];
    float* out = (float*)d_out;

    int total = BB * HW4;                 // 80000 threads
    int blocks = (total + 255) / 256;     // 313 blocks
    k_stats<<<blocks, 256>>>(bev, pri);

    k_select_sum<<<BB, 1024>>>();

    k_finalize<<<1, 32>>>(dx, dy, dt, out);
}